// round 4
// baseline (speedup 1.0000x reference)
#include <cuda_runtime.h>

// Problem constants
#define B_    2
#define S_    2048
#define D_    1024
#define H_    16
#define DK_   64
#define BH_   (B_*H_)        // 32
#define MROWS (B_*S_)        // 4096
#define OUT_OFF ((size_t)B_*S_*D_)   // 4194304 floats: start of attention_weights

// Scratch (device globals — no allocation allowed)
__device__ float g_q[BH_*S_*DK_];    // [B,H,S,DK]
__device__ float g_k[BH_*S_*DK_];
__device__ float g_v[BH_*S_*DK_];
__device__ float g_ctx[MROWS*D_];    // [B,S,D] merged-head context

// ---------------------------------------------------------------------------
// Tiled fp32 GEMM building blocks: BM=BN=64, BK=16, 256 threads, 4x4 per thread
// A is staged transposed in smem (Ast[k][m], padded stride 68) so the inner
// loop does 2x LDS.128 per 16 FMA.
// ---------------------------------------------------------------------------

// QKV projection: out = X[4096,1024] @ W[1024,1024] + bias, written split-head
// dst_sel: 0 -> g_q, 1 -> g_k, 2 -> g_v   layout [B,H,S,DK]
__global__ void proj_kernel(const float* __restrict__ X,
                            const float* __restrict__ W,
                            const float* __restrict__ bias,
                            int dst_sel)
{
    __shared__ float Ast[16][68];
    __shared__ float Bs[16][64];
    const int m0 = blockIdx.y * 64;
    const int n0 = blockIdx.x * 64;
    const int tid = threadIdx.x;
    const int tx = tid & 15, ty = tid >> 4;
    float acc[4][4] = {};

    for (int k0 = 0; k0 < D_; k0 += 16) {
        {
            int ar = tid >> 2, ac = (tid & 3) * 4;
            float4 v = *(const float4*)&X[(size_t)(m0 + ar) * D_ + k0 + ac];
            Ast[ac+0][ar] = v.x; Ast[ac+1][ar] = v.y;
            Ast[ac+2][ar] = v.z; Ast[ac+3][ar] = v.w;
        }
        {
            int br = tid >> 4, bc = (tid & 15) * 4;
            *(float4*)&Bs[br][bc] = *(const float4*)&W[(size_t)(k0 + br) * D_ + n0 + bc];
        }
        __syncthreads();
        #pragma unroll
        for (int kk = 0; kk < 16; kk++) {
            float4 a4 = *(const float4*)&Ast[kk][ty*4];
            float4 b4 = *(const float4*)&Bs[kk][tx*4];
            float av[4] = {a4.x, a4.y, a4.z, a4.w};
            float bv[4] = {b4.x, b4.y, b4.z, b4.w};
            #pragma unroll
            for (int i = 0; i < 4; i++)
                #pragma unroll
                for (int j = 0; j < 4; j++)
                    acc[i][j] += av[i] * bv[j];
        }
        __syncthreads();
    }

    float* dst = (dst_sel == 0) ? g_q : (dst_sel == 1) ? g_k : g_v;
    #pragma unroll
    for (int i = 0; i < 4; i++) {
        int m = m0 + ty*4 + i;
        int b = m >> 11, s = m & (S_ - 1);
        #pragma unroll
        for (int j = 0; j < 4; j++) {
            int n = n0 + tx*4 + j;
            int h = n >> 6, d = n & (DK_ - 1);
            dst[(((size_t)(b*H_ + h))*S_ + s)*DK_ + d] = acc[i][j] + bias[n];
        }
    }
}

// Scores: C[bh] = (Q[bh] @ K[bh]^T) * 0.125  -> attn region of d_out (raw softmax input)
// NT GEMM: M=N=2048, K=64
__global__ void scores_kernel(float* __restrict__ attn)
{
    __shared__ float Ast[16][68];
    __shared__ float Bst[16][68];
    const int bh = blockIdx.z;
    const float* Q = g_q + (size_t)bh * S_ * DK_;
    const float* Km = g_k + (size_t)bh * S_ * DK_;
    float* C = attn + (size_t)bh * S_ * S_;
    const int m0 = blockIdx.y * 64;
    const int n0 = blockIdx.x * 64;
    const int tid = threadIdx.x;
    const int tx = tid & 15, ty = tid >> 4;
    float acc[4][4] = {};

    #pragma unroll
    for (int k0 = 0; k0 < DK_; k0 += 16) {
        {
            int ar = tid >> 2, ac = (tid & 3) * 4;
            float4 v = *(const float4*)&Q[(size_t)(m0 + ar) * DK_ + k0 + ac];
            Ast[ac+0][ar] = v.x; Ast[ac+1][ar] = v.y;
            Ast[ac+2][ar] = v.z; Ast[ac+3][ar] = v.w;
        }
        {
            int nr = tid >> 2, nc = (tid & 3) * 4;
            float4 v = *(const float4*)&Km[(size_t)(n0 + nr) * DK_ + k0 + nc];
            Bst[nc+0][nr] = v.x; Bst[nc+1][nr] = v.y;
            Bst[nc+2][nr] = v.z; Bst[nc+3][nr] = v.w;
        }
        __syncthreads();
        #pragma unroll
        for (int kk = 0; kk < 16; kk++) {
            float4 a4 = *(const float4*)&Ast[kk][ty*4];
            float4 b4 = *(const float4*)&Bst[kk][tx*4];
            float av[4] = {a4.x, a4.y, a4.z, a4.w};
            float bv[4] = {b4.x, b4.y, b4.z, b4.w};
            #pragma unroll
            for (int i = 0; i < 4; i++)
                #pragma unroll
                for (int j = 0; j < 4; j++)
                    acc[i][j] += av[i] * bv[j];
        }
        __syncthreads();
    }

    #pragma unroll
    for (int i = 0; i < 4; i++) {
        int m = m0 + ty*4 + i;
        #pragma unroll
        for (int j = 0; j < 4; j++) {
            int n = n0 + tx*4 + j;
            C[(size_t)m * S_ + n] = acc[i][j] * 0.125f;
        }
    }
}

// Row softmax in place over attn rows of length S_=2048. One block per row.
__global__ void softmax_kernel(float* __restrict__ attn)
{
    const size_t row = blockIdx.x;
    float* p = attn + row * (size_t)S_;
    const int tid = threadIdx.x;
    const int lane = tid & 31, wid = tid >> 5;
    __shared__ float red[8];

    float4 v0 = ((const float4*)p)[tid];
    float4 v1 = ((const float4*)p)[tid + 256];

    float m = fmaxf(fmaxf(fmaxf(v0.x, v0.y), fmaxf(v0.z, v0.w)),
                    fmaxf(fmaxf(v1.x, v1.y), fmaxf(v1.z, v1.w)));
    #pragma unroll
    for (int o = 16; o; o >>= 1) m = fmaxf(m, __shfl_xor_sync(0xffffffffu, m, o));
    if (lane == 0) red[wid] = m;
    __syncthreads();
    if (tid == 0) {
        float mm = red[0];
        #pragma unroll
        for (int i = 1; i < 8; i++) mm = fmaxf(mm, red[i]);
        red[0] = mm;
    }
    __syncthreads();
    m = red[0];
    __syncthreads();

    float4 e0, e1;
    e0.x = __expf(v0.x - m); e0.y = __expf(v0.y - m);
    e0.z = __expf(v0.z - m); e0.w = __expf(v0.w - m);
    e1.x = __expf(v1.x - m); e1.y = __expf(v1.y - m);
    e1.z = __expf(v1.z - m); e1.w = __expf(v1.w - m);

    float s = (e0.x + e0.y + e0.z + e0.w) + (e1.x + e1.y + e1.z + e1.w);
    #pragma unroll
    for (int o = 16; o; o >>= 1) s += __shfl_xor_sync(0xffffffffu, s, o);
    if (lane == 0) red[wid] = s;
    __syncthreads();
    if (tid == 0) {
        float ss = 0.f;
        #pragma unroll
        for (int i = 0; i < 8; i++) ss += red[i];
        red[0] = ss;
    }
    __syncthreads();
    float inv = 1.0f / red[0];

    e0.x *= inv; e0.y *= inv; e0.z *= inv; e0.w *= inv;
    e1.x *= inv; e1.y *= inv; e1.z *= inv; e1.w *= inv;
    ((float4*)p)[tid] = e0;
    ((float4*)p)[tid + 256] = e1;
}

// Context: ctx[b,s,h*64+d] = sum_k attn[bh,s,k] * V[bh,k,d]
// NN GEMM per bh: M=2048, N=64, K=2048
__global__ void av_kernel(const float* __restrict__ attn)
{
    __shared__ float Ast[16][68];
    __shared__ float Bs[16][64];
    const int bh = blockIdx.z;
    const int b = bh >> 4, h = bh & 15;
    const float* A = attn + (size_t)bh * S_ * S_;
    const float* V = g_v + (size_t)bh * S_ * DK_;
    const int m0 = blockIdx.y * 64;
    const int tid = threadIdx.x;
    const int tx = tid & 15, ty = tid >> 4;
    float acc[4][4] = {};

    for (int k0 = 0; k0 < S_; k0 += 16) {
        {
            int ar = tid >> 2, ac = (tid & 3) * 4;
            float4 v = *(const float4*)&A[(size_t)(m0 + ar) * S_ + k0 + ac];
            Ast[ac+0][ar] = v.x; Ast[ac+1][ar] = v.y;
            Ast[ac+2][ar] = v.z; Ast[ac+3][ar] = v.w;
        }
        {
            int br = tid >> 4, bc = (tid & 15) * 4;
            *(float4*)&Bs[br][bc] = *(const float4*)&V[(size_t)(k0 + br) * DK_ + bc];
        }
        __syncthreads();
        #pragma unroll
        for (int kk = 0; kk < 16; kk++) {
            float4 a4 = *(const float4*)&Ast[kk][ty*4];
            float4 b4 = *(const float4*)&Bs[kk][tx*4];
            float av[4] = {a4.x, a4.y, a4.z, a4.w};
            float bv[4] = {b4.x, b4.y, b4.z, b4.w};
            #pragma unroll
            for (int i = 0; i < 4; i++)
                #pragma unroll
                for (int j = 0; j < 4; j++)
                    acc[i][j] += av[i] * bv[j];
        }
        __syncthreads();
    }

    #pragma unroll
    for (int i = 0; i < 4; i++) {
        int s = m0 + ty*4 + i;
        #pragma unroll
        for (int j = 0; j < 4; j++) {
            int d = tx*4 + j;
            g_ctx[((size_t)(b*S_ + s))*D_ + h*DK_ + d] = acc[i][j];
        }
    }
}

// Output projection: out = ctx[4096,1024] @ Wo + bo -> d_out (plain row-major)
__global__ void out_kernel(const float* __restrict__ W,
                           const float* __restrict__ bias,
                           float* __restrict__ out)
{
    __shared__ float Ast[16][68];
    __shared__ float Bs[16][64];
    const int m0 = blockIdx.y * 64;
    const int n0 = blockIdx.x * 64;
    const int tid = threadIdx.x;
    const int tx = tid & 15, ty = tid >> 4;
    float acc[4][4] = {};

    for (int k0 = 0; k0 < D_; k0 += 16) {
        {
            int ar = tid >> 2, ac = (tid & 3) * 4;
            float4 v = *(const float4*)&g_ctx[(size_t)(m0 + ar) * D_ + k0 + ac];
            Ast[ac+0][ar] = v.x; Ast[ac+1][ar] = v.y;
            Ast[ac+2][ar] = v.z; Ast[ac+3][ar] = v.w;
        }
        {
            int br = tid >> 4, bc = (tid & 15) * 4;
            *(float4*)&Bs[br][bc] = *(const float4*)&W[(size_t)(k0 + br) * D_ + n0 + bc];
        }
        __syncthreads();
        #pragma unroll
        for (int kk = 0; kk < 16; kk++) {
            float4 a4 = *(const float4*)&Ast[kk][ty*4];
            float4 b4 = *(const float4*)&Bs[kk][tx*4];
            float av[4] = {a4.x, a4.y, a4.z, a4.w};
            float bv[4] = {b4.x, b4.y, b4.z, b4.w};
            #pragma unroll
            for (int i = 0; i < 4; i++)
                #pragma unroll
                for (int j = 0; j < 4; j++)
                    acc[i][j] += av[i] * bv[j];
        }
        __syncthreads();
    }

    #pragma unroll
    for (int i = 0; i < 4; i++) {
        int m = m0 + ty*4 + i;
        #pragma unroll
        for (int j = 0; j < 4; j++) {
            int n = n0 + tx*4 + j;
            out[(size_t)m * D_ + n] = acc[i][j] + bias[n];
        }
    }
}

extern "C" void kernel_launch(void* const* d_in, const int* in_sizes, int n_in,
                              void* d_out, int out_size)
{
    (void)in_sizes; (void)n_in; (void)out_size;
    const float* query = (const float*)d_in[0];
    const float* key_  = (const float*)d_in[1];
    const float* value = (const float*)d_in[2];
    const float* Wq = (const float*)d_in[3];
    const float* bq = (const float*)d_in[4];
    const float* Wk = (const float*)d_in[5];
    const float* bk = (const float*)d_in[6];
    const float* Wv = (const float*)d_in[7];
    const float* bv = (const float*)d_in[8];
    const float* Wo = (const float*)d_in[9];
    const float* bo = (const float*)d_in[10];

    float* out  = (float*)d_out;
    float* attn = out + OUT_OFF;

    dim3 tpb(256);
    dim3 grid_proj(D_ / 64, MROWS / 64);          // 16 x 64
    proj_kernel<<<grid_proj, tpb>>>(query, Wq, bq, 0);
    proj_kernel<<<grid_proj, tpb>>>(key_,  Wk, bk, 1);
    proj_kernel<<<grid_proj, tpb>>>(value, Wv, bv, 2);

    dim3 grid_sc(S_ / 64, S_ / 64, BH_);          // 32 x 32 x 32
    scores_kernel<<<grid_sc, tpb>>>(attn);

    softmax_kernel<<<BH_ * S_, tpb>>>(attn);      // 65536 blocks

    dim3 grid_av(1, S_ / 64, BH_);                // 1 x 32 x 32
    av_kernel<<<grid_av, tpb>>>(attn);

    dim3 grid_out(D_ / 64, MROWS / 64);           // 16 x 64
    out_kernel<<<grid_out, tpb>>>(Wo, bo, out);
}

// round 7
// speedup vs baseline: 2.1379x; 2.1379x over previous
#include <cuda_runtime.h>
#include <cuda_bf16.h>
#include <stdint.h>

// Problem constants
#define S_ 2048
#define D_ 1024
#define HN 16
#define DK 64
#define BH 32
#define MR 4096                      // B*S
#define OUT_OFF ((size_t)MR*D_)      // start of attention_weights in d_out

// Scratch (device globals — no allocation allowed)
__device__ float g_q[BH*S_*DK];      // [bh][s][dk]
__device__ float g_k[BH*S_*DK];
__device__ float g_v[BH*S_*DK];
__device__ float g_vt[BH*DK*S_];     // [bh][dk][s]
__device__ float g_ctx[(size_t)MR*D_];
__device__ float g_wt[(size_t)4*D_*D_];  // Wq^T, Wk^T, Wv^T, Wo^T  [n][k]

// ---------------------------------------------------------------------------
// Helpers
// ---------------------------------------------------------------------------
__device__ __forceinline__ uint32_t smem_u32(const void* p) {
    uint32_t a;
    asm("{ .reg .u64 t; cvta.to.shared.u64 t, %1; cvt.u32.u64 %0, t; }" : "=r"(a) : "l"(p));
    return a;
}

__device__ __forceinline__ void ldmx4(uint32_t& r0, uint32_t& r1, uint32_t& r2,
                                      uint32_t& r3, uint32_t addr) {
    asm volatile("ldmatrix.sync.aligned.m8n8.x4.shared.b16 {%0,%1,%2,%3}, [%4];"
                 : "=r"(r0), "=r"(r1), "=r"(r2), "=r"(r3) : "r"(addr));
}

__device__ __forceinline__ void mma16816(float* c, const uint32_t* a, const uint32_t* b) {
    asm volatile("mma.sync.aligned.m16n8k16.row.col.f32.bf16.bf16.f32 "
                 "{%0,%1,%2,%3}, {%4,%5,%6,%7}, {%8,%9}, {%0,%1,%2,%3};"
                 : "+f"(c[0]), "+f"(c[1]), "+f"(c[2]), "+f"(c[3])
                 : "r"(a[0]), "r"(a[1]), "r"(a[2]), "r"(a[3]), "r"(b[0]), "r"(b[1]));
}

// Split two fp32 into packed-bf16x2 (hi) and packed-bf16x2 residual (lo)
__device__ __forceinline__ void split2(float x, float y, uint32_t& hi, uint32_t& lo) {
    __nv_bfloat162 h2 = __float22bfloat162_rn(make_float2(x, y));
    uint32_t hb = *reinterpret_cast<uint32_t*>(&h2);
    float hx = __uint_as_float(hb << 16);
    float hy = __uint_as_float(hb & 0xFFFF0000u);
    __nv_bfloat162 l2 = __float22bfloat162_rn(make_float2(x - hx, y - hy));
    hi = hb;
    lo = *reinterpret_cast<uint32_t*>(&l2);
}

// Swizzled byte offset within a [rows x 32 bf16] region (64B rows, 16B chunks)
__device__ __forceinline__ uint32_t swo(int r, int cc) {
    return (uint32_t)(r * 64 + ((cc ^ ((r >> 1) & 3)) * 16));
}

// ---------------------------------------------------------------------------
// Tiled transpose: dst[c][r] = src[r][c].  dsel 0..3 -> g_wt slice, 4 -> g_vt
// blockDim (32,8); grid (C/32, R/32, batch)
// ---------------------------------------------------------------------------
__global__ void transpose_kernel(const float* __restrict__ src, int R, int C, int dsel)
{
    __shared__ float t[32][33];
    float* dbase = (dsel < 4) ? (g_wt + (size_t)dsel * D_ * D_) : g_vt;
    const float* s = (src ? src : g_v) + (size_t)blockIdx.z * R * C;
    float* d = dbase + (size_t)blockIdx.z * R * C;
    int r0 = blockIdx.y * 32, c0 = blockIdx.x * 32;
    int x = threadIdx.x, y = threadIdx.y;
    #pragma unroll
    for (int i = 0; i < 32; i += 8)
        t[y + i][x] = s[(size_t)(r0 + y + i) * C + c0 + x];
    __syncthreads();
    #pragma unroll
    for (int i = 0; i < 32; i += 8)
        d[(size_t)(c0 + y + i) * R + r0 + x] = t[x][y + i];
}

// ---------------------------------------------------------------------------
// bf16x3 NT GEMM via mma.sync: D[m][n] = scale * sum_k A[m][k]*B[n][k] (+bias)
// MODE 0: proj   A=ext X[4096,1024], B=g_wt[sel], K=1024 -> split-head q/k/v
// MODE 1: scores A=g_q[bh], B=g_k[bh], K=64, *0.125 -> attn (Cext)
// MODE 2: av     A=attn[bh] (Aext), B=g_vt[bh], K=2048, TN=64 -> g_ctx
// MODE 3: out    A=g_ctx, B=g_wt[3], K=1024, +bias -> Cext (d_out)
// 256 threads (8 warps: 4M x 2N). Tile 128 x TN, K-chunk 32 fp32.
// ---------------------------------------------------------------------------
template <int MODE>
__global__ __launch_bounds__(256, 1)
void mma_kernel(const float* __restrict__ Aext,
                const float* __restrict__ bias,
                float* __restrict__ Cext, int sel)
{
    constexpr int TN = (MODE == 2) ? 64 : 128;
    constexpr int KT = (MODE == 1) ? 64 : ((MODE == 2) ? 2048 : 1024);
    constexpr int LD = (MODE == 1) ? 64 : ((MODE == 2) ? 2048 : 1024);
    constexpr int NC = KT / 32;
    constexpr int WN = TN / 2;        // warp n-span
    constexpr int NT = WN / 8;        // n-tiles per warp (8 or 4)
    constexpr int NB = TN * 4 / 256;  // B 16B-chunks per thread (2 or 1)
    constexpr int BOF = 16384;        // B-hi offset within stage
    constexpr int SS = 16384 + 2 * TN * 64;  // stage bytes

    extern __shared__ char sm[];
    const uint32_t smb = smem_u32(sm);
    const int tid = threadIdx.x, lane = tid & 31, wid = tid >> 5;
    const int wm = wid & 3, wn = wid >> 2;
    const int m0 = blockIdx.y * 128;
    const int n0 = blockIdx.x * TN;
    const int bh = blockIdx.z;

    const float* Ap;
    const float* Bp;
    if (MODE == 0) {
        Ap = Aext + (size_t)m0 * D_;
        Bp = g_wt + (size_t)sel * D_ * D_ + (size_t)n0 * D_;
    } else if (MODE == 1) {
        Ap = g_q + ((size_t)bh * S_ + m0) * DK;
        Bp = g_k + ((size_t)bh * S_ + n0) * DK;
    } else if (MODE == 2) {
        Ap = Aext + (size_t)bh * S_ * S_ + (size_t)m0 * S_;
        Bp = g_vt + (size_t)bh * DK * S_;
    } else {
        Ap = g_ctx + (size_t)m0 * D_;
        Bp = g_wt + (size_t)3 * D_ * D_ + (size_t)n0 * D_;
    }

    float c[2][NT][4] = {};
    float4 ra[2][2];
    float4 rb[NB][2];

#define LOADCH(k0) do {                                                          \
    _Pragma("unroll")                                                            \
    for (int t = 0; t < 2; t++) {                                                \
        int ci = tid + t * 256; int r = ci >> 2, cc = ci & 3;                    \
        const float* p = Ap + (size_t)r * LD + (k0) + cc * 8;                    \
        ra[t][0] = *(const float4*)p; ra[t][1] = *(const float4*)(p + 4);        \
    }                                                                            \
    _Pragma("unroll")                                                            \
    for (int t = 0; t < NB; t++) {                                               \
        int ci = tid + t * 256; int r = ci >> 2, cc = ci & 3;                    \
        const float* p = Bp + (size_t)r * LD + (k0) + cc * 8;                    \
        rb[t][0] = *(const float4*)p; rb[t][1] = *(const float4*)(p + 4);        \
    }                                                                            \
} while (0)

#define STORECH(buf) do {                                                        \
    char* bs = sm + (buf) * SS;                                                  \
    _Pragma("unroll")                                                            \
    for (int t = 0; t < 2; t++) {                                                \
        int ci = tid + t * 256; int r = ci >> 2, cc = ci & 3;                    \
        uint32_t o = swo(r, cc);                                                 \
        uint32_t h0,l0,h1,l1,h2,l2,h3,l3;                                        \
        split2(ra[t][0].x, ra[t][0].y, h0, l0);                                  \
        split2(ra[t][0].z, ra[t][0].w, h1, l1);                                  \
        split2(ra[t][1].x, ra[t][1].y, h2, l2);                                  \
        split2(ra[t][1].z, ra[t][1].w, h3, l3);                                  \
        *(uint4*)(bs + o)        = make_uint4(h0, h1, h2, h3);                   \
        *(uint4*)(bs + 8192 + o) = make_uint4(l0, l1, l2, l3);                   \
    }                                                                            \
    _Pragma("unroll")                                                            \
    for (int t = 0; t < NB; t++) {                                               \
        int ci = tid + t * 256; int r = ci >> 2, cc = ci & 3;                    \
        uint32_t o = swo(r, cc);                                                 \
        uint32_t h0,l0,h1,l1,h2,l2,h3,l3;                                        \
        split2(rb[t][0].x, rb[t][0].y, h0, l0);                                  \
        split2(rb[t][0].z, rb[t][0].w, h1, l1);                                  \
        split2(rb[t][1].x, rb[t][1].y, h2, l2);                                  \
        split2(rb[t][1].z, rb[t][1].w, h3, l3);                                  \
        *(uint4*)(bs + BOF + o)            = make_uint4(h0, h1, h2, h3);         \
        *(uint4*)(bs + BOF + TN * 64 + o)  = make_uint4(l0, l1, l2, l3);         \
    }                                                                            \
} while (0)

    LOADCH(0);
    STORECH(0);
    __syncthreads();

    for (int ch = 0; ch < NC; ch++) {
        if (ch + 1 < NC) LOADCH((ch + 1) * 32);

        {   // MMA on buffer ch&1
            const uint32_t bb = smb + (uint32_t)(ch & 1) * SS;
            #pragma unroll
            for (int ks = 0; ks < 2; ks++) {
                uint32_t ah[2][4], al[2][4], bhf[NT][2], blf[NT][2];
                const int cc = ks * 2 + (lane >> 4);
                #pragma unroll
                for (int i = 0; i < 2; i++) {
                    int r = wm * 32 + i * 16 + (lane & 15);
                    uint32_t o = swo(r, cc);
                    ldmx4(ah[i][0], ah[i][1], ah[i][2], ah[i][3], bb + o);
                    ldmx4(al[i][0], al[i][1], al[i][2], al[i][3], bb + 8192 + o);
                }
                #pragma unroll
                for (int g = 0; g < NT / 2; g++) {
                    int r = wn * WN + g * 16 + (lane & 15);
                    uint32_t o = swo(r, cc);
                    uint32_t t0, t1, t2, t3;
                    ldmx4(t0, t1, t2, t3, bb + BOF + o);
                    bhf[2*g][0] = t0; bhf[2*g+1][0] = t1;
                    bhf[2*g][1] = t2; bhf[2*g+1][1] = t3;
                    ldmx4(t0, t1, t2, t3, bb + BOF + TN * 64 + o);
                    blf[2*g][0] = t0; blf[2*g+1][0] = t1;
                    blf[2*g][1] = t2; blf[2*g+1][1] = t3;
                }
                #pragma unroll
                for (int i = 0; i < 2; i++)
                    #pragma unroll
                    for (int j = 0; j < NT; j++) {
                        mma16816(c[i][j], ah[i], bhf[j]);
                        mma16816(c[i][j], ah[i], blf[j]);
                        mma16816(c[i][j], al[i], bhf[j]);
                    }
            }
        }

        if (ch + 1 < NC) STORECH((ch + 1) & 1);
        __syncthreads();
    }

    // ---------------- epilogue ----------------
    const int mr0 = m0 + wm * 32 + (lane >> 2);
    const int nl0 = wn * WN + 2 * (lane & 3);

    #pragma unroll
    for (int i = 0; i < 2; i++) {
        #pragma unroll
        for (int j = 0; j < NT; j++) {
            int n_loc = nl0 + j * 8;
            #pragma unroll
            for (int half = 0; half < 2; half++) {
                int m = mr0 + i * 16 + half * 8;
                float v0 = c[i][j][half * 2 + 0];
                float v1 = c[i][j][half * 2 + 1];
                if constexpr (MODE == 0) {
                    int ng = n0 + n_loc;
                    float2 bv = *(const float2*)(bias + ng);
                    int h = ng >> 6, d = ng & 63;
                    int b2 = m >> 11, s = m & (S_ - 1);
                    float* dst = (sel == 0 ? g_q : sel == 1 ? g_k : g_v)
                               + (((size_t)(b2 * HN + h)) * S_ + s) * DK + d;
                    *(float2*)dst = make_float2(v0 + bv.x, v1 + bv.y);
                } else if constexpr (MODE == 1) {
                    float* dst = Cext + (size_t)bh * S_ * S_ + (size_t)m * S_ + n0 + n_loc;
                    *(float2*)dst = make_float2(v0 * 0.125f, v1 * 0.125f);
                } else if constexpr (MODE == 2) {
                    int b2 = bh >> 4, h = bh & 15;
                    float* dst = g_ctx + ((size_t)(b2 * S_ + m)) * D_ + h * DK + n_loc;
                    *(float2*)dst = make_float2(v0, v1);
                } else {
                    int ng = n0 + n_loc;
                    float2 bv = *(const float2*)(bias + ng);
                    float* dst = Cext + (size_t)m * D_ + ng;
                    *(float2*)dst = make_float2(v0 + bv.x, v1 + bv.y);
                }
            }
        }
    }
#undef LOADCH
#undef STORECH
}

// ---------------------------------------------------------------------------
// Row softmax in place over attn rows of length 2048. One block per row.
// ---------------------------------------------------------------------------
__global__ void softmax_kernel(float* __restrict__ attn)
{
    const size_t row = blockIdx.x;
    float* p = attn + row * (size_t)S_;
    const int tid = threadIdx.x;
    const int lane = tid & 31, wid = tid >> 5;
    __shared__ float red[8];

    float4 v0 = ((const float4*)p)[tid];
    float4 v1 = ((const float4*)p)[tid + 256];

    float m = fmaxf(fmaxf(fmaxf(v0.x, v0.y), fmaxf(v0.z, v0.w)),
                    fmaxf(fmaxf(v1.x, v1.y), fmaxf(v1.z, v1.w)));
    #pragma unroll
    for (int o = 16; o; o >>= 1) m = fmaxf(m, __shfl_xor_sync(0xffffffffu, m, o));
    if (lane == 0) red[wid] = m;
    __syncthreads();
    if (tid == 0) {
        float mm = red[0];
        #pragma unroll
        for (int i = 1; i < 8; i++) mm = fmaxf(mm, red[i]);
        red[0] = mm;
    }
    __syncthreads();
    m = red[0];
    __syncthreads();

    float4 e0, e1;
    e0.x = __expf(v0.x - m); e0.y = __expf(v0.y - m);
    e0.z = __expf(v0.z - m); e0.w = __expf(v0.w - m);
    e1.x = __expf(v1.x - m); e1.y = __expf(v1.y - m);
    e1.z = __expf(v1.z - m); e1.w = __expf(v1.w - m);

    float s = (e0.x + e0.y + e0.z + e0.w) + (e1.x + e1.y + e1.z + e1.w);
    #pragma unroll
    for (int o = 16; o; o >>= 1) s += __shfl_xor_sync(0xffffffffu, s, o);
    if (lane == 0) red[wid] = s;
    __syncthreads();
    if (tid == 0) {
        float ss = 0.f;
        #pragma unroll
        for (int i = 0; i < 8; i++) ss += red[i];
        red[0] = ss;
    }
    __syncthreads();
    float inv = 1.0f / red[0];

    e0.x *= inv; e0.y *= inv; e0.z *= inv; e0.w *= inv;
    e1.x *= inv; e1.y *= inv; e1.z *= inv; e1.w *= inv;
    ((float4*)p)[tid] = e0;
    ((float4*)p)[tid + 256] = e1;
}

extern "C" void kernel_launch(void* const* d_in, const int* in_sizes, int n_in,
                              void* d_out, int out_size)
{
    (void)in_sizes; (void)n_in; (void)out_size;
    const float* query = (const float*)d_in[0];
    const float* key_  = (const float*)d_in[1];
    const float* value = (const float*)d_in[2];
    const float* Wq = (const float*)d_in[3];
    const float* bq = (const float*)d_in[4];
    const float* Wk = (const float*)d_in[5];
    const float* bk = (const float*)d_in[6];
    const float* Wv = (const float*)d_in[7];
    const float* bv = (const float*)d_in[8];
    const float* Wo = (const float*)d_in[9];
    const float* bo = (const float*)d_in[10];

    float* out  = (float*)d_out;
    float* attn = out + OUT_OFF;

    const int SM128 = 2 * (16384 + 2 * 128 * 64);  // 65536
    const int SM64  = 2 * (16384 + 2 * 64 * 64);   // 49152
    cudaFuncSetAttribute(mma_kernel<0>, cudaFuncAttributeMaxDynamicSharedMemorySize, SM128);
    cudaFuncSetAttribute(mma_kernel<1>, cudaFuncAttributeMaxDynamicSharedMemorySize, SM128);
    cudaFuncSetAttribute(mma_kernel<2>, cudaFuncAttributeMaxDynamicSharedMemorySize, SM64);
    cudaFuncSetAttribute(mma_kernel<3>, cudaFuncAttributeMaxDynamicSharedMemorySize, SM128);

    dim3 tpbT(32, 8);
    // Weight transposes: g_wt[sel] = W^T
    transpose_kernel<<<dim3(32, 32, 1), tpbT>>>(Wq, D_, D_, 0);
    transpose_kernel<<<dim3(32, 32, 1), tpbT>>>(Wk, D_, D_, 1);
    transpose_kernel<<<dim3(32, 32, 1), tpbT>>>(Wv, D_, D_, 2);
    transpose_kernel<<<dim3(32, 32, 1), tpbT>>>(Wo, D_, D_, 3);

    // QKV projections -> g_q/g_k/g_v split-head
    mma_kernel<0><<<dim3(8, 32), 256, SM128>>>(query, bq, nullptr, 0);
    mma_kernel<0><<<dim3(8, 32), 256, SM128>>>(key_,  bk, nullptr, 1);
    mma_kernel<0><<<dim3(8, 32), 256, SM128>>>(value, bv, nullptr, 2);

    // V transpose per head: g_vt[bh] = V[bh]^T
    transpose_kernel<<<dim3(2, 64, 32), tpbT>>>(nullptr, S_, DK, 4);

    // Scores = 0.125 * Q K^T -> attn
    mma_kernel<1><<<dim3(16, 16, 32), 256, SM128>>>(nullptr, nullptr, attn, 0);

    // Softmax rows in place
    softmax_kernel<<<BH * S_, 256>>>(attn);

    // Context = attn @ V -> g_ctx
    mma_kernel<2><<<dim3(1, 16, 32), 256, SM64>>>(attn, nullptr, nullptr, 0);

    // Output = ctx @ Wo + bo -> d_out
    mma_kernel<3><<<dim3(8, 32), 256, SM128>>>(nullptr, bo, out, 0);
}

// round 10
// speedup vs baseline: 2.5346x; 1.1856x over previous
#include <cuda_runtime.h>
#include <cuda_bf16.h>
#include <stdint.h>

// Problem constants
#define S_ 2048
#define D_ 1024
#define HN 16
#define DK 64
#define BH 32
#define MR 4096                      // B*S
#define OUT_OFF ((size_t)MR*D_)      // start of attention_weights in d_out

// Scratch (device globals — no allocation allowed; referenced ONLY in device code)
__device__ float g_v[BH*S_*DK];                    // [bh][s][dk] fp32 (pre-transpose)
__device__ __nv_bfloat16 g_qh[BH*S_*DK], g_ql[BH*S_*DK];   // [bh][s][dk]
__device__ __nv_bfloat16 g_kh[BH*S_*DK], g_kl[BH*S_*DK];
__device__ __nv_bfloat16 g_vth[BH*DK*S_], g_vtl[BH*DK*S_]; // [bh][dk][s]
__device__ __nv_bfloat16 g_xh[(size_t)3*MR*D_], g_xl[(size_t)3*MR*D_];   // split inputs
__device__ __nv_bfloat16 g_wth[(size_t)4*D_*D_], g_wtl[(size_t)4*D_*D_]; // W^T hi/lo
__device__ __nv_bfloat16 g_ctxh[(size_t)MR*D_], g_ctxl[(size_t)MR*D_];

// ---------------------------------------------------------------------------
// Helpers
// ---------------------------------------------------------------------------
__device__ __forceinline__ uint32_t smem_u32(const void* p) {
    uint32_t a;
    asm("{ .reg .u64 t; cvta.to.shared.u64 t, %1; cvt.u32.u64 %0, t; }" : "=r"(a) : "l"(p));
    return a;
}
__device__ __forceinline__ void ldmx4(uint32_t& r0, uint32_t& r1, uint32_t& r2,
                                      uint32_t& r3, uint32_t addr) {
    asm volatile("ldmatrix.sync.aligned.m8n8.x4.shared.b16 {%0,%1,%2,%3}, [%4];"
                 : "=r"(r0), "=r"(r1), "=r"(r2), "=r"(r3) : "r"(addr));
}
__device__ __forceinline__ void mma16816(float* c, const uint32_t* a, const uint32_t* b) {
    asm volatile("mma.sync.aligned.m16n8k16.row.col.f32.bf16.bf16.f32 "
                 "{%0,%1,%2,%3}, {%4,%5,%6,%7}, {%8,%9}, {%0,%1,%2,%3};"
                 : "+f"(c[0]), "+f"(c[1]), "+f"(c[2]), "+f"(c[3])
                 : "r"(a[0]), "r"(a[1]), "r"(a[2]), "r"(a[3]), "r"(b[0]), "r"(b[1]));
}
#define CPA16(dst, src) \
    asm volatile("cp.async.cg.shared.global [%0], [%1], 16;" :: "r"(dst), "l"(src) : "memory")
#define CPA_COMMIT() asm volatile("cp.async.commit_group;" ::: "memory")
#define CPA_WAIT(n)  asm volatile("cp.async.wait_group %0;" :: "n"(n) : "memory")

// Split two fp32 into packed-bf16x2 (hi) and packed-bf16x2 residual (lo)
__device__ __forceinline__ void split2(float x, float y, uint32_t& hi, uint32_t& lo) {
    __nv_bfloat162 h2 = __float22bfloat162_rn(make_float2(x, y));
    uint32_t hb = *reinterpret_cast<uint32_t*>(&h2);
    float hx = __uint_as_float(hb << 16);
    float hy = __uint_as_float(hb & 0xFFFF0000u);
    __nv_bfloat162 l2 = __float22bfloat162_rn(make_float2(x - hx, y - hy));
    hi = hb;
    lo = *reinterpret_cast<uint32_t*>(&l2);
}
__device__ __forceinline__ void st_pair(__nv_bfloat16* dh, __nv_bfloat16* dl,
                                        size_t off, float v0, float v1) {
    uint32_t h, l; split2(v0, v1, h, l);
    *(uint32_t*)(dh + off) = h;
    *(uint32_t*)(dl + off) = l;
}
// Swizzled byte offset within a [rows x 32 bf16] region (64B rows, 16B chunks)
__device__ __forceinline__ uint32_t swo(int r, int cc) {
    return (uint32_t)(r * 64 + ((cc ^ ((r >> 1) & 3)) * 16));
}

// ---------------------------------------------------------------------------
// Elementwise split: fp32 -> bf16 hi/lo into g_xh/g_xl slot. 4 elems/thread.
// ---------------------------------------------------------------------------
__global__ void split_kernel(const float* __restrict__ src, int slot)
{
    __nv_bfloat16* dh = g_xh + (size_t)slot * MR * D_;
    __nv_bfloat16* dl = g_xl + (size_t)slot * MR * D_;
    size_t i = ((size_t)blockIdx.x * blockDim.x + threadIdx.x) * 4;
    float4 v = *(const float4*)(src + i);
    uint32_t h0, l0, h1, l1;
    split2(v.x, v.y, h0, l0);
    split2(v.z, v.w, h1, l1);
    *(uint2*)(dh + i) = make_uint2(h0, h1);
    *(uint2*)(dl + i) = make_uint2(l0, l1);
}

// ---------------------------------------------------------------------------
// Transpose + split: dst_hi/lo[c][r] = bf16split(src[r][c])
// dsel 0..3 -> g_wth/g_wtl slice (src=W); dsel 4 -> g_vth/g_vtl (src=g_v)
// grid (C/32, R/32, batch), block (32,8)
// ---------------------------------------------------------------------------
__global__ void transpose_split_kernel(const float* __restrict__ src,
                                       int R, int C, int dsel)
{
    __shared__ float t[32][33];
    __nv_bfloat16* dh;
    __nv_bfloat16* dl;
    const float* sbase;
    if (dsel < 4) {
        dh = g_wth + (size_t)dsel * D_ * D_;
        dl = g_wtl + (size_t)dsel * D_ * D_;
        sbase = src;
    } else {
        dh = g_vth; dl = g_vtl; sbase = g_v;
    }
    const float* s = sbase + (size_t)blockIdx.z * R * C;
    __nv_bfloat16* oh = dh + (size_t)blockIdx.z * R * C;
    __nv_bfloat16* ol = dl + (size_t)blockIdx.z * R * C;
    int r0 = blockIdx.y * 32, c0 = blockIdx.x * 32;
    int x = threadIdx.x, y = threadIdx.y;
    #pragma unroll
    for (int i = 0; i < 32; i += 8)
        t[y + i][x] = s[(size_t)(r0 + y + i) * C + c0 + x];
    __syncthreads();
    #pragma unroll
    for (int i = 0; i < 32; i += 8) {
        float v = t[x][y + i];
        __nv_bfloat16 hb = __float2bfloat16(v);
        float r = v - __bfloat162float(hb);
        size_t o = (size_t)(c0 + y + i) * R + r0 + x;
        oh[o] = hb;
        ol[o] = __float2bfloat16(r);
    }
}

// ---------------------------------------------------------------------------
// MMA block: NT n-tiles/warp. A-hi at bbA, A-lo at bbA+ALO.
// B-hi at bbB, B-lo at bbB+BLO. Accumulates into c[2][NT][4].
// ---------------------------------------------------------------------------
#define MMA_BLOCK(NT, bbA, ALO, bbB, BLO)                                       \
    do {                                                                        \
        _Pragma("unroll")                                                       \
        for (int ks = 0; ks < 2; ks++) {                                        \
            uint32_t ah[2][4], al[2][4], bhf[NT][2], blf[NT][2];                \
            const int cc = ks * 2 + (lane >> 4);                                \
            _Pragma("unroll")                                                   \
            for (int i = 0; i < 2; i++) {                                       \
                int r = wm * 32 + i * 16 + (lane & 15);                         \
                uint32_t o = swo(r, cc);                                        \
                ldmx4(ah[i][0], ah[i][1], ah[i][2], ah[i][3], (bbA) + o);       \
                ldmx4(al[i][0], al[i][1], al[i][2], al[i][3], (bbA) + (ALO) + o);\
            }                                                                   \
            _Pragma("unroll")                                                   \
            for (int g = 0; g < NT / 2; g++) {                                  \
                int r = wn * (NT * 8) + g * 16 + (lane & 15);                   \
                uint32_t o = swo(r, cc);                                        \
                uint32_t t0, t1, t2, t3;                                        \
                ldmx4(t0, t1, t2, t3, (bbB) + o);                               \
                bhf[2*g][0] = t0; bhf[2*g+1][0] = t1;                           \
                bhf[2*g][1] = t2; bhf[2*g+1][1] = t3;                           \
                ldmx4(t0, t1, t2, t3, (bbB) + (BLO) + o);                       \
                blf[2*g][0] = t0; blf[2*g+1][0] = t1;                           \
                blf[2*g][1] = t2; blf[2*g+1][1] = t3;                           \
            }                                                                   \
            _Pragma("unroll")                                                   \
            for (int i = 0; i < 2; i++)                                         \
                _Pragma("unroll")                                               \
                for (int j = 0; j < NT; j++) {                                  \
                    mma16816(c[i][j], ah[i], bhf[j]);                           \
                    mma16816(c[i][j], ah[i], blf[j]);                           \
                    mma16816(c[i][j], al[i], bhf[j]);                           \
                }                                                               \
        }                                                                       \
    } while (0)

// ---------------------------------------------------------------------------
// gemm_ps<MODE>: pre-split A,B (bf16 hi/lo, LD=1024, K=1024), tile 128x128.
// Operand arrays selected IN DEVICE CODE (never pass __device__ symbols from host).
// MODE 0: A=g_x[sel], B=g_wt[sel] -> q/k bf16 pairs or v fp32 (split-head) + bias
// MODE 1: A=g_ctx,    B=g_wt[3]   -> d_out fp32 + bias
// smem: 2 buffers x 32KB {AH 8K | AL 8K | BH 8K | BL 8K}
// ---------------------------------------------------------------------------
template <int MODE>
__global__ __launch_bounds__(256)
void gemm_ps(const float* __restrict__ bias, float* __restrict__ Cext, int sel)
{
    constexpr int NC = 32;
    extern __shared__ char sm[];
    const uint32_t smb = smem_u32(sm);
    const int tid = threadIdx.x, lane = tid & 31, wid = tid >> 5;
    const int wm = wid & 3, wn = wid >> 2;
    const int m0 = blockIdx.y * 128;
    const int n0 = blockIdx.x * 128;

    const __nv_bfloat16 *Ah, *Al, *Bh, *Bl;
    if (MODE == 0) {
        Ah = g_xh + (size_t)sel * MR * D_;  Al = g_xl + (size_t)sel * MR * D_;
        Bh = g_wth + (size_t)sel * D_ * D_; Bl = g_wtl + (size_t)sel * D_ * D_;
    } else {
        Ah = g_ctxh;                        Al = g_ctxl;
        Bh = g_wth + (size_t)3 * D_ * D_;   Bl = g_wtl + (size_t)3 * D_ * D_;
    }
    Ah += (size_t)m0 * D_; Al += (size_t)m0 * D_;
    Bh += (size_t)n0 * D_; Bl += (size_t)n0 * D_;

    float c[2][8][4] = {};

#define ISSUE_PS(ch) do {                                                       \
    uint32_t base = smb + (uint32_t)((ch) & 1) * 32768;                         \
    int k0 = (ch) * 32;                                                         \
    _Pragma("unroll")                                                           \
    for (int t = 0; t < 2; t++) {                                               \
        int id = tid + t * 256; int r = id >> 2, cc = id & 3;                   \
        uint32_t o = swo(r, cc);                                                \
        size_t go = (size_t)r * D_ + k0 + cc * 8;                               \
        CPA16(base + o,         Ah + go);                                       \
        CPA16(base + 8192 + o,  Al + go);                                       \
        CPA16(base + 16384 + o, Bh + go);                                       \
        CPA16(base + 24576 + o, Bl + go);                                       \
    }                                                                           \
    CPA_COMMIT();                                                               \
} while (0)

    ISSUE_PS(0);
    for (int ch = 0; ch < NC; ch++) {
        if (ch + 1 < NC) { ISSUE_PS(ch + 1); CPA_WAIT(1); }
        else             { CPA_WAIT(0); }
        __syncthreads();
        const uint32_t bb = smb + (uint32_t)(ch & 1) * 32768;
        MMA_BLOCK(8, bb, 8192, bb + 16384, 8192);
        __syncthreads();
    }
#undef ISSUE_PS

    // Epilogue
    const int mr0 = m0 + wm * 32 + (lane >> 2);
    const int nl0 = wn * 64 + 2 * (lane & 3);
    #pragma unroll
    for (int i = 0; i < 2; i++)
        #pragma unroll
        for (int j = 0; j < 8; j++) {
            int n_loc = nl0 + j * 8;
            int ng = n0 + n_loc;
            float2 bv = *(const float2*)(bias + ng);
            #pragma unroll
            for (int half = 0; half < 2; half++) {
                int m = mr0 + i * 16 + half * 8;
                float v0 = c[i][j][half * 2 + 0] + bv.x;
                float v1 = c[i][j][half * 2 + 1] + bv.y;
                if constexpr (MODE == 0) {
                    int h = ng >> 6, d = ng & 63;
                    int b2 = m >> 11, s = m & (S_ - 1);
                    size_t off = (((size_t)(b2 * HN + h)) * S_ + s) * DK + d;
                    if (sel == 0)      st_pair(g_qh, g_ql, off, v0, v1);
                    else if (sel == 1) st_pair(g_kh, g_kl, off, v0, v1);
                    else               *(float2*)(g_v + off) = make_float2(v0, v1);
                } else {
                    *(float2*)(Cext + (size_t)m * D_ + ng) = make_float2(v0, v1);
                }
            }
        }
}

// ---------------------------------------------------------------------------
// scores: 0.125 * Q K^T per head, K=64 single shot, tile 128x128.
// smem 64KB: QH [2 chunks x 8K] | QL +16384 | KH +32768 | KL +49152
// ---------------------------------------------------------------------------
__global__ __launch_bounds__(256)
void scores_mma(float* __restrict__ attn)
{
    extern __shared__ char sm[];
    const uint32_t smb = smem_u32(sm);
    const int tid = threadIdx.x, lane = tid & 31, wid = tid >> 5;
    const int wm = wid & 3, wn = wid >> 2;
    const int m0 = blockIdx.y * 128;
    const int n0 = blockIdx.x * 128;
    const int bh = blockIdx.z;

    const __nv_bfloat16* Qh = g_qh + ((size_t)bh * S_ + m0) * DK;
    const __nv_bfloat16* Ql = g_ql + ((size_t)bh * S_ + m0) * DK;
    const __nv_bfloat16* Kh = g_kh + ((size_t)bh * S_ + n0) * DK;
    const __nv_bfloat16* Kl = g_kl + ((size_t)bh * S_ + n0) * DK;

    #pragma unroll
    for (int t = 0; t < 4; t++) {
        int id = tid + t * 256;
        int ch = id >> 9, r = (id >> 2) & 127, cc = id & 3;
        uint32_t o = (uint32_t)ch * 8192 + swo(r, cc);
        size_t go = (size_t)r * DK + ch * 32 + cc * 8;
        CPA16(smb + o,         Qh + go);
        CPA16(smb + 16384 + o, Ql + go);
        CPA16(smb + 32768 + o, Kh + go);
        CPA16(smb + 49152 + o, Kl + go);
    }
    CPA_COMMIT();
    CPA_WAIT(0);
    __syncthreads();

    float c[2][8][4] = {};
    #pragma unroll
    for (int chk = 0; chk < 2; chk++) {
        const uint32_t bb = smb + (uint32_t)chk * 8192;
        MMA_BLOCK(8, bb, 16384, bb + 32768, 16384);
    }

    const int mr0 = m0 + wm * 32 + (lane >> 2);
    const int nl0 = wn * 64 + 2 * (lane & 3);
    float* C = attn + (size_t)bh * S_ * S_;
    #pragma unroll
    for (int i = 0; i < 2; i++)
        #pragma unroll
        for (int j = 0; j < 8; j++) {
            int ng = n0 + nl0 + j * 8;
            #pragma unroll
            for (int half = 0; half < 2; half++) {
                int m = mr0 + i * 16 + half * 8;
                *(float2*)(C + (size_t)m * S_ + ng) =
                    make_float2(c[i][j][half*2+0] * 0.125f, c[i][j][half*2+1] * 0.125f);
            }
        }
}

// ---------------------------------------------------------------------------
// av: ctx = attn @ V. A = fp32 attn (in-kernel split), B = pre-split V^T.
// tile 128x64, K=2048, NC=64. smem 2 x 24KB {AH 8K | AL 8K | BH 4K | BL 4K}
// ---------------------------------------------------------------------------
__global__ __launch_bounds__(256)
void av_mma(const float* __restrict__ attn)
{
    constexpr int NC = 64;
    extern __shared__ char sm[];
    const uint32_t smb = smem_u32(sm);
    const int tid = threadIdx.x, lane = tid & 31, wid = tid >> 5;
    const int wm = wid & 3, wn = wid >> 2;
    const int m0 = blockIdx.y * 128;
    const int bh = blockIdx.z;

    const float* Ap = attn + (size_t)bh * S_ * S_ + (size_t)m0 * S_;
    const __nv_bfloat16* Bh_ = g_vth + (size_t)bh * DK * S_;
    const __nv_bfloat16* Bl_ = g_vtl + (size_t)bh * DK * S_;

    float c[2][4][4] = {};
    float4 ra[2][2];

#define LOADA(k0) do {                                                          \
    _Pragma("unroll")                                                           \
    for (int t = 0; t < 2; t++) {                                               \
        int id = tid + t * 256; int r = id >> 2, cc = id & 3;                   \
        const float* p = Ap + (size_t)r * S_ + (k0) + cc * 8;                   \
        ra[t][0] = *(const float4*)p; ra[t][1] = *(const float4*)(p + 4);       \
    }                                                                           \
} while (0)
#define ISSUEB(ch) do {                                                         \
    uint32_t base = smb + (uint32_t)((ch) & 1) * 24576;                         \
    int r = tid >> 2, cc = tid & 3;                                             \
    uint32_t o = swo(r, cc);                                                    \
    size_t go = (size_t)r * S_ + (ch) * 32 + cc * 8;                            \
    CPA16(base + 16384 + o, Bh_ + go);                                          \
    CPA16(base + 20480 + o, Bl_ + go);                                          \
    CPA_COMMIT();                                                               \
} while (0)
#define STSA(ch) do {                                                           \
    char* bs = sm + ((ch) & 1) * 24576;                                         \
    _Pragma("unroll")                                                           \
    for (int t = 0; t < 2; t++) {                                               \
        int id = tid + t * 256; int r = id >> 2, cc = id & 3;                   \
        uint32_t o = swo(r, cc);                                                \
        uint32_t h0,l0,h1,l1,h2,l2,h3,l3;                                       \
        split2(ra[t][0].x, ra[t][0].y, h0, l0);                                 \
        split2(ra[t][0].z, ra[t][0].w, h1, l1);                                 \
        split2(ra[t][1].x, ra[t][1].y, h2, l2);                                 \
        split2(ra[t][1].z, ra[t][1].w, h3, l3);                                 \
        *(uint4*)(bs + o)        = make_uint4(h0, h1, h2, h3);                  \
        *(uint4*)(bs + 8192 + o) = make_uint4(l0, l1, l2, l3);                  \
    }                                                                           \
} while (0)

    LOADA(0); ISSUEB(0); STSA(0); CPA_WAIT(0);
    __syncthreads();

    for (int ch = 0; ch < NC; ch++) {
        if (ch + 1 < NC) { LOADA((ch + 1) * 32); ISSUEB(ch + 1); }
        const uint32_t bb = smb + (uint32_t)(ch & 1) * 24576;
        MMA_BLOCK(4, bb, 8192, bb + 16384, 4096);
        if (ch + 1 < NC) STSA(ch + 1);
        CPA_WAIT(0);
        __syncthreads();
    }
#undef LOADA
#undef ISSUEB
#undef STSA

    // Epilogue -> ctx bf16 pairs
    const int b2 = bh >> 4, h = bh & 15;
    const int mr0 = m0 + wm * 32 + (lane >> 2);
    const int nl0 = wn * 32 + 2 * (lane & 3);
    #pragma unroll
    for (int i = 0; i < 2; i++)
        #pragma unroll
        for (int j = 0; j < 4; j++) {
            int n_loc = nl0 + j * 8;
            #pragma unroll
            for (int half = 0; half < 2; half++) {
                int m = mr0 + i * 16 + half * 8;
                size_t off = ((size_t)(b2 * S_ + m)) * D_ + h * DK + n_loc;
                st_pair(g_ctxh, g_ctxl, off, c[i][j][half*2+0], c[i][j][half*2+1]);
            }
        }
}

// ---------------------------------------------------------------------------
// Row softmax in place over attn rows of length 2048. One block per row.
// ---------------------------------------------------------------------------
__global__ void softmax_kernel(float* __restrict__ attn)
{
    const size_t row = blockIdx.x;
    float* p = attn + row * (size_t)S_;
    const int tid = threadIdx.x;
    const int lane = tid & 31, wid = tid >> 5;
    __shared__ float red[8];

    float4 v0 = ((const float4*)p)[tid];
    float4 v1 = ((const float4*)p)[tid + 256];

    float m = fmaxf(fmaxf(fmaxf(v0.x, v0.y), fmaxf(v0.z, v0.w)),
                    fmaxf(fmaxf(v1.x, v1.y), fmaxf(v1.z, v1.w)));
    #pragma unroll
    for (int o = 16; o; o >>= 1) m = fmaxf(m, __shfl_xor_sync(0xffffffffu, m, o));
    if (lane == 0) red[wid] = m;
    __syncthreads();
    if (tid == 0) {
        float mm = red[0];
        #pragma unroll
        for (int i = 1; i < 8; i++) mm = fmaxf(mm, red[i]);
        red[0] = mm;
    }
    __syncthreads();
    m = red[0];
    __syncthreads();

    float4 e0, e1;
    e0.x = __expf(v0.x - m); e0.y = __expf(v0.y - m);
    e0.z = __expf(v0.z - m); e0.w = __expf(v0.w - m);
    e1.x = __expf(v1.x - m); e1.y = __expf(v1.y - m);
    e1.z = __expf(v1.z - m); e1.w = __expf(v1.w - m);

    float s = (e0.x + e0.y + e0.z + e0.w) + (e1.x + e1.y + e1.z + e1.w);
    #pragma unroll
    for (int o = 16; o; o >>= 1) s += __shfl_xor_sync(0xffffffffu, s, o);
    if (lane == 0) red[wid] = s;
    __syncthreads();
    if (tid == 0) {
        float ss = 0.f;
        #pragma unroll
        for (int i = 0; i < 8; i++) ss += red[i];
        red[0] = ss;
    }
    __syncthreads();
    float inv = 1.0f / red[0];

    e0.x *= inv; e0.y *= inv; e0.z *= inv; e0.w *= inv;
    e1.x *= inv; e1.y *= inv; e1.z *= inv; e1.w *= inv;
    ((float4*)p)[tid] = e0;
    ((float4*)p)[tid + 256] = e1;
}

extern "C" void kernel_launch(void* const* d_in, const int* in_sizes, int n_in,
                              void* d_out, int out_size)
{
    (void)in_sizes; (void)n_in; (void)out_size;
    const float* query = (const float*)d_in[0];
    const float* key_  = (const float*)d_in[1];
    const float* value = (const float*)d_in[2];
    const float* Wq = (const float*)d_in[3];
    const float* bq = (const float*)d_in[4];
    const float* Wk = (const float*)d_in[5];
    const float* bk = (const float*)d_in[6];
    const float* Wv = (const float*)d_in[7];
    const float* bv = (const float*)d_in[8];
    const float* Wo = (const float*)d_in[9];
    const float* bo = (const float*)d_in[10];

    float* out  = (float*)d_out;
    float* attn = out + OUT_OFF;

    cudaFuncSetAttribute(gemm_ps<0>, cudaFuncAttributeMaxDynamicSharedMemorySize, 65536);
    cudaFuncSetAttribute(gemm_ps<1>, cudaFuncAttributeMaxDynamicSharedMemorySize, 65536);
    cudaFuncSetAttribute(scores_mma, cudaFuncAttributeMaxDynamicSharedMemorySize, 65536);
    cudaFuncSetAttribute(av_mma,     cudaFuncAttributeMaxDynamicSharedMemorySize, 49152);

    // --- one-time pre-split / transpose passes (dst selected device-side) ---
    dim3 tpbT(32, 8);
    transpose_split_kernel<<<dim3(32, 32, 1), tpbT>>>(Wq, D_, D_, 0);
    transpose_split_kernel<<<dim3(32, 32, 1), tpbT>>>(Wk, D_, D_, 1);
    transpose_split_kernel<<<dim3(32, 32, 1), tpbT>>>(Wv, D_, D_, 2);
    transpose_split_kernel<<<dim3(32, 32, 1), tpbT>>>(Wo, D_, D_, 3);
    split_kernel<<<MR*D_/1024, 256>>>(query, 0);
    split_kernel<<<MR*D_/1024, 256>>>(key_,  1);
    split_kernel<<<MR*D_/1024, 256>>>(value, 2);

    // --- QKV projections (operands selected device-side by sel) ---
    gemm_ps<0><<<dim3(8, 32), 256, 65536>>>(bq, nullptr, 0);
    gemm_ps<0><<<dim3(8, 32), 256, 65536>>>(bk, nullptr, 1);
    gemm_ps<0><<<dim3(8, 32), 256, 65536>>>(bv, nullptr, 2);

    // V^T hi/lo per head (src = g_v device-side)
    transpose_split_kernel<<<dim3(2, 64, 32), tpbT>>>(nullptr, S_, DK, 4);

    // Scores, softmax, AV, output projection
    scores_mma<<<dim3(16, 16, 32), 256, 65536>>>(attn);
    softmax_kernel<<<BH * S_, 256>>>(attn);
    av_mma<<<dim3(1, 16, 32), 256, 49152>>>(attn);
    gemm_ps<1><<<dim3(8, 32), 256, 65536>>>(bo, out, 0);
}